// round 2
// baseline (speedup 1.0000x reference)
#include <cuda_runtime.h>
#include <cstdint>
#include <cstddef>

#define LHW   53
#define NP    2809            // 53*53 patches
#define NM    8192
#define KTOT  3072
#define PADP  10
#define BM    128
#define BN    128
#define BK    16
#define NKT   (KTOT / BK)     // 192
#define WROWS 35              // padded-image row window per patch tile
#define IMG_ELEMS (3 * WROWS * 84)

__device__ float               g_memsq[NM];
__device__ unsigned long long  g_best[NP];
__device__ int                 g_rows[NP];
__device__ float               g_max;

// ---------------------------------------------------------------------------
// K1: mem_sq[n] = sum_k mem[n,k]^2 ; also (re)init g_best every call
// ---------------------------------------------------------------------------
__global__ void memsq_kernel(const float* __restrict__ mem) {
    int n = blockIdx.x;
    const float* row = mem + (size_t)n * KTOT;
    float s = 0.f;
    for (int i = threadIdx.x; i < KTOT; i += 128) {
        float v = row[i];
        s = fmaf(v, v, s);
    }
    #pragma unroll
    for (int o = 16; o > 0; o >>= 1) s += __shfl_down_sync(0xFFFFFFFFu, s, o);
    __shared__ float part[4];
    if ((threadIdx.x & 31) == 0) part[threadIdx.x >> 5] = s;
    __syncthreads();
    if (threadIdx.x == 0) g_memsq[n] = (part[0] + part[1]) + (part[2] + part[3]);
    if (threadIdx.x == 32 && n < NP) g_best[n] = 0xFFFFFFFFFFFFFFFFull;
}

// ---------------------------------------------------------------------------
// K2: fused patches@mem^T GEMM + argmin(mem_sq - 2*score)
// A synthesized from image window in SMEM, B double-buffered via registers.
// ---------------------------------------------------------------------------
__global__ __launch_bounds__(256, 2)
void gemm_argmin_kernel(const float* __restrict__ image,
                        const float* __restrict__ mem) {
    extern __shared__ unsigned char smem_raw[];
    unsigned long long* best_s = (unsigned long long*)smem_raw;          // 128*8 B
    float* img_s = (float*)(smem_raw + 1024);                            // 35280 B
    float* As    = img_s + IMG_ELEMS;                                    // [2][BK][BM]
    float* Bs    = As + 2 * BK * BM;                                     // [2][BK][BN]

    const int tid = threadIdx.x;
    const int mt  = blockIdx.x;   // mem tile   (64)
    const int pt  = blockIdx.y;   // patch tile (22)

    const int rlo = (pt * BM) / LHW;   // first padded-image row this tile needs

    // Load padded-image window (zeros outside image), layout [3][WROWS][84]
    for (int idx = tid; idx < IMG_ELEMS; idx += 256) {
        int c   = idx / (WROWS * 84);
        int rem = idx - c * (WROWS * 84);
        int il  = rem / 84;
        int j   = rem - il * 84;
        int I   = rlo + il;
        float v = 0.f;
        if (I >= PADP && I < PADP + 64 && j >= PADP && j < PADP + 64)
            v = image[((I - PADP) * 64 + (j - PADP)) * 3 + c];
        img_s[idx] = v;
    }
    if (tid < BM) best_s[tid] = 0xFFFFFFFFFFFFFFFFull;

    // A-fill thread mapping: column pa, k-rows ka, ka+2, ka+4, ...
    const int  pa   = tid & 127;
    const int  ka   = tid >> 7;            // 0 or 1
    const int  pr_a = pt * BM + pa;
    const bool va   = pr_a < NP;
    const int  prc  = va ? pr_a : 0;
    const int  ph_a = prc / LHW;
    const int  pw_a = prc - ph_a * LHW;
    const int  rb   = ph_a - rlo;          // local row base in window

    // B-fill thread mapping: float4 per (row nb, k-quad kq), rows nb and nb+64
    const int nb = tid >> 2;               // 0..63
    const int kq = (tid & 3) * 4;
    const float* bptr = mem + ((size_t)(mt * BN + nb)) * KTOT + kq;

    const int m0 = (tid >> 4) * 8;
    const int n0 = (tid & 15) * 8;

    float acc[8][8];
    #pragma unroll
    for (int i = 0; i < 8; i++)
        #pragma unroll
        for (int j = 0; j < 8; j++) acc[i][j] = 0.f;

    // Prologue: B global loads for kt=0 (independent of SMEM)
    float4 pb0 = *(const float4*)(bptr);
    float4 pb1 = *(const float4*)(bptr + (size_t)64 * KTOT);

    __syncthreads();  // image window + best_s ready

    // Fill buffer 0
    #pragma unroll
    for (int i = 0; i < 8; i++) {
        int k  = ka + 2 * i;
        int kh = (k >> 5) & 31;    // kt=0 -> kg = k, c = 0
        int kw = k & 31;
        float v = 0.f;
        if (va) v = img_s[(rb + kh) * 84 + pw_a + kw];
        As[k * BM + pa] = v;
    }
    Bs[(kq + 0) * BN + nb]      = pb0.x;
    Bs[(kq + 1) * BN + nb]      = pb0.y;
    Bs[(kq + 2) * BN + nb]      = pb0.z;
    Bs[(kq + 3) * BN + nb]      = pb0.w;
    Bs[(kq + 0) * BN + nb + 64] = pb1.x;
    Bs[(kq + 1) * BN + nb + 64] = pb1.y;
    Bs[(kq + 2) * BN + nb + 64] = pb1.z;
    Bs[(kq + 3) * BN + nb + 64] = pb1.w;
    __syncthreads();

    int buf = 0;
    for (int kt = 0; kt < NKT; kt++) {
        float4 qb0, qb1;
        float  ap[8];
        const bool more = (kt + 1) < NKT;
        if (more) {
            qb0 = *(const float4*)(bptr + (size_t)(kt + 1) * BK);
            qb1 = *(const float4*)(bptr + (size_t)64 * KTOT + (size_t)(kt + 1) * BK);
            #pragma unroll
            for (int i = 0; i < 8; i++) {
                int kg = (kt + 1) * BK + ka + 2 * i;
                int c  = kg >> 10;
                int kh = (kg >> 5) & 31;
                int kw = kg & 31;
                ap[i] = va ? img_s[c * (WROWS * 84) + (rb + kh) * 84 + pw_a + kw] : 0.f;
            }
        }
        const float* Ab = As + buf * (BK * BM);
        const float* Bb = Bs + buf * (BK * BN);
        #pragma unroll
        for (int k = 0; k < BK; k++) {
            float a[8], b[8];
            *(float4*)&a[0] = *(const float4*)(Ab + k * BM + m0);
            *(float4*)&a[4] = *(const float4*)(Ab + k * BM + m0 + 4);
            *(float4*)&b[0] = *(const float4*)(Bb + k * BN + n0);
            *(float4*)&b[4] = *(const float4*)(Bb + k * BN + n0 + 4);
            #pragma unroll
            for (int i = 0; i < 8; i++)
                #pragma unroll
                for (int j = 0; j < 8; j++)
                    acc[i][j] = fmaf(a[i], b[j], acc[i][j]);
        }
        if (more) {
            float* An = As + (buf ^ 1) * (BK * BM);
            float* Bn = Bs + (buf ^ 1) * (BK * BN);
            #pragma unroll
            for (int i = 0; i < 8; i++) An[(ka + 2 * i) * BM + pa] = ap[i];
            Bn[(kq + 0) * BN + nb]      = qb0.x;
            Bn[(kq + 1) * BN + nb]      = qb0.y;
            Bn[(kq + 2) * BN + nb]      = qb0.z;
            Bn[(kq + 3) * BN + nb]      = qb0.w;
            Bn[(kq + 0) * BN + nb + 64] = qb1.x;
            Bn[(kq + 1) * BN + nb + 64] = qb1.y;
            Bn[(kq + 2) * BN + nb + 64] = qb1.z;
            Bn[(kq + 3) * BN + nb + 64] = qb1.w;
        }
        __syncthreads();
        buf ^= 1;
    }

    // Epilogue: dist = mem_sq[n] - 2*score; argmin packed (orderedFloat<<32 | n)
    #pragma unroll
    for (int i = 0; i < 8; i++) {
        int p  = m0 + i;
        int pr = pt * BM + p;
        if (pr < NP) {
            unsigned long long bk = 0xFFFFFFFFFFFFFFFFull;
            #pragma unroll
            for (int j = 0; j < 8; j++) {
                int n = mt * BN + n0 + j;
                float dist = g_memsq[n] - 2.f * acc[i][j];
                unsigned int ub = __float_as_uint(dist);
                ub = (ub & 0x80000000u) ? ~ub : (ub | 0x80000000u);
                unsigned long long key =
                    ((unsigned long long)ub << 32) | (unsigned int)n;
                bk = key < bk ? key : bk;
            }
            atomicMin(&best_s[p], bk);
        }
    }
    __syncthreads();
    if (tid < BM) {
        int pr = pt * BM + tid;
        if (pr < NP) atomicMin(&g_best[pr], best_s[tid]);
    }
}

// ---------------------------------------------------------------------------
// K3: rows[p] = mapping[argmin index]
// ---------------------------------------------------------------------------
__global__ void resolve_kernel(const int* __restrict__ mapping) {
    int p = blockIdx.x * blockDim.x + threadIdx.x;
    if (p < NP) {
        unsigned int n = (unsigned int)(g_best[p] & 0xFFFFFFFFull);
        g_rows[p] = mapping[n];
    }
}

// ---------------------------------------------------------------------------
// K4: deterministic overlap-add as a gather. out[(i*64+j)*3+c] (HWC).
// ---------------------------------------------------------------------------
__global__ void recon_kernel(const float* __restrict__ mem2,
                             float* __restrict__ out) {
    __shared__ int rows_s[NP];
    for (int t = threadIdx.x; t < NP; t += 256) rows_s[t] = g_rows[t];
    __syncthreads();
    int idx = blockIdx.x * 256 + threadIdx.x;      // 0..12287 exactly
    int c = idx % 3;
    int j = (idx / 3) & 63;
    int i = idx / 192;
    int I = i + PADP, J = j + PADP;
    int khlo = max(0, I - (LHW - 1));
    int khhi = min(31, I);
    int kwlo = max(0, J - (LHW - 1));
    int kwhi = min(31, J);
    float s = 0.f;
    for (int kh = khlo; kh <= khhi; kh++) {
        int rbase = (I - kh) * LHW;
        int obase = c * 1024 + kh * 32;
        for (int kw = kwlo; kw <= kwhi; kw++) {
            int r = rows_s[rbase + (J - kw)];
            s += mem2[(size_t)r * KTOT + obase + kw];
        }
    }
    out[idx] = s;
}

// ---------------------------------------------------------------------------
// K5: global max of out (single block); K6: scale by 1/max
// ---------------------------------------------------------------------------
__global__ void max_kernel(const float* __restrict__ o) {
    float m = -3.402823466e38f;
    for (int i = threadIdx.x; i < 12288; i += 1024) m = fmaxf(m, o[i]);
    #pragma unroll
    for (int off = 16; off > 0; off >>= 1)
        m = fmaxf(m, __shfl_xor_sync(0xFFFFFFFFu, m, off));
    __shared__ float red[32];
    if ((threadIdx.x & 31) == 0) red[threadIdx.x >> 5] = m;
    __syncthreads();
    if (threadIdx.x < 32) {
        m = red[threadIdx.x];
        #pragma unroll
        for (int off = 16; off > 0; off >>= 1)
            m = fmaxf(m, __shfl_xor_sync(0xFFFFFFFFu, m, off));
        if (threadIdx.x == 0) g_max = m;
    }
}

__global__ void scale_kernel(float* __restrict__ o) {
    int i = blockIdx.x * 256 + threadIdx.x;
    if (i < 12288) o[i] = o[i] / g_max;
}

// ---------------------------------------------------------------------------
extern "C" void kernel_launch(void* const* d_in, const int* in_sizes, int n_in,
                              void* d_out, int out_size) {
    const float* image   = (const float*)d_in[0];
    const float* mem     = (const float*)d_in[1];
    const float* mem2    = (const float*)d_in[2];
    const int*   mapping = (const int*)d_in[3];
    float*       out     = (float*)d_out;

    const size_t SMEM_BYTES =
        1024 + (size_t)IMG_ELEMS * 4 + (size_t)2 * BK * BM * 4 + (size_t)2 * BK * BN * 4; // 69072
    cudaFuncSetAttribute(gemm_argmin_kernel,
                         cudaFuncAttributeMaxDynamicSharedMemorySize,
                         (int)SMEM_BYTES);

    memsq_kernel<<<NM, 128>>>(mem);
    dim3 grid(NM / BN, (NP + BM - 1) / BM);   // 64 x 22
    gemm_argmin_kernel<<<grid, 256, SMEM_BYTES>>>(image, mem);
    resolve_kernel<<<(NP + 255) / 256, 256>>>(mapping);
    recon_kernel<<<48, 256>>>(mem2, out);
    max_kernel<<<1, 1024>>>(out);
    scale_kernel<<<48, 256>>>(out);
}

// round 4
// speedup vs baseline: 3.6095x; 3.6095x over previous
#include <cuda_runtime.h>
#include <cstdint>
#include <cstddef>

#define LHW   53
#define NP    2809
#define NM    8192
#define KTOT  3072
#define WR    35
#define IMG_ELEMS (3 * WR * 84)   // 8820

// ---------------- device scratch -------------------------------------------
__device__ float     g_adist[(size_t)NP * NM];   // 92 MB approx distances
__device__ unsigned  g_amin[NP];
__device__ float     g_memsq[NM];
__device__ int       g_rows[NP];
__device__ float     g_part[32 * 12288];
__device__ float     g_max;

__device__ __forceinline__ unsigned enc(float x) {
    unsigned u = __float_as_uint(x);
    return (u & 0x80000000u) ? ~u : (u | 0x80000000u);
}
__device__ __forceinline__ float dec(unsigned u) {
    unsigned b = (u & 0x80000000u) ? (u & 0x7FFFFFFFu) : ~u;
    return __uint_as_float(b);
}
__device__ __forceinline__ unsigned tf32_bits(float x) {
    unsigned y;
    asm("cvt.rna.tf32.f32 %0, %1;" : "=r"(y) : "f"(x));
    return y;
}
__device__ __forceinline__ void mma1688(float* d, const unsigned* a, const unsigned* b) {
    asm volatile(
        "mma.sync.aligned.m16n8k8.row.col.f32.tf32.tf32.f32 "
        "{%0,%1,%2,%3}, {%4,%5,%6,%7}, {%8,%9}, {%0,%1,%2,%3};"
        : "+f"(d[0]), "+f"(d[1]), "+f"(d[2]), "+f"(d[3])
        : "r"(a[0]), "r"(a[1]), "r"(a[2]), "r"(a[3]), "r"(b[0]), "r"(b[1]));
}
#define SW128(b) ((b) ^ (((b) >> 3) & 0x70))

// ---------------------------------------------------------------------------
// K1: mem_sq from ORIGINAL fp32 mem; init g_amin
// ---------------------------------------------------------------------------
__global__ void memsq_kernel(const float* __restrict__ mem) {
    int n = blockIdx.x;
    const float* row = mem + (size_t)n * KTOT;
    float s = 0.f;
    for (int i = threadIdx.x; i < KTOT; i += 128) {
        float v = row[i];
        s = fmaf(v, v, s);
    }
    #pragma unroll
    for (int o = 16; o > 0; o >>= 1) s += __shfl_down_sync(0xFFFFFFFFu, s, o);
    __shared__ float part[4];
    if ((threadIdx.x & 31) == 0) part[threadIdx.x >> 5] = s;
    __syncthreads();
    if (threadIdx.x == 0) g_memsq[n] = (part[0] + part[1]) + (part[2] + part[3]);
    if (threadIdx.x == 32 && n < NP) g_amin[n] = 0xFFFFFFFFu;
}

// ---------------------------------------------------------------------------
// K2: tf32 mma.sync approx GEMM. CTA 128x128, K in 32-chunks (4 k8-steps).
// A synthesized per-lane from tf32 image window in SMEM; B double-buffered SW128.
// Writes approx dist (92MB) + per-patch approx min.
// ---------------------------------------------------------------------------
#define B_BUF_BYTES 16384
#define IMG_OFF     32768
#define GEMM_SMEM   (IMG_OFF + IMG_ELEMS * 4)   // 68048

__global__ __launch_bounds__(256, 2)
void gemm_approx_kernel(const float* __restrict__ image,
                        const float* __restrict__ mem) {
    extern __shared__ __align__(1024) unsigned char smem[];
    unsigned* img_w = (unsigned*)(smem + IMG_OFF);

    const int tid  = threadIdx.x;
    const int lane = tid & 31;
    const int wid  = tid >> 5;
    const int widm = wid >> 2;        // 0..1
    const int widn = wid & 3;         // 0..3
    const int gid  = lane >> 2;       // 0..7
    const int tig  = lane & 3;        // 0..3

    const int bn0 = blockIdx.x * 128;
    const int pm0 = blockIdx.y * 128;
    const int rlo = pm0 / LHW;

    // image window as tf32 bit patterns, [3][WR][84]
    for (int idx = tid; idx < IMG_ELEMS; idx += 256) {
        int c   = idx / (WR * 84);
        int rem = idx - c * (WR * 84);
        int il  = rem / 84;
        int j   = rem - il * 84;
        int I   = rlo + il;
        float v = 0.f;
        if (I >= 10 && I < 74 && j >= 10 && j < 74)
            v = image[((I - 10) * 64 + (j - 10)) * 3 + c];
        img_w[idx] = tf32_bits(v);
    }

    // per-lane A row bases (incl. +tig), 4 m-tiles x {r, r+8}
    int abase[4][2];
    #pragma unroll
    for (int mt2 = 0; mt2 < 4; mt2++)
        #pragma unroll
        for (int h = 0; h < 2; h++) {
            int pr = pm0 + widm * 64 + mt2 * 16 + gid + 8 * h;
            pr = pr < NP ? pr : NP - 1;
            int ph = pr / LHW;
            abase[mt2][h] = (ph - rlo) * 84 + (pr - LHW * ph) + tig;
        }

    // B fill thread mapping: 4 float4 per thread per chunk
    // f = tid + 256*j : row = f>>3 (0..127), q = f&7
    const int brow = tid >> 3;
    const int bq   = tid & 7;
    const float* bsrc0 = mem + (size_t)(bn0 + brow) * KTOT + bq * 4;

    // B frag address helpers
    int nbase[4], nxr[4];
    #pragma unroll
    for (int nt2 = 0; nt2 < 4; nt2++) {
        int nl = widn * 32 + nt2 * 8 + gid;
        nbase[nt2] = nl * 128;
        nxr[nt2]   = (nl & 7) << 4;
    }

    float acc[4][4][4];
    #pragma unroll
    for (int i = 0; i < 4; i++)
        #pragma unroll
        for (int j = 0; j < 4; j++)
            #pragma unroll
            for (int k = 0; k < 4; k++) acc[i][j][k] = 0.f;

    // prologue: fill buffer 0 (chunk 0)
    {
        float4 v[4];
        #pragma unroll
        for (int j = 0; j < 4; j++)
            v[j] = *(const float4*)(bsrc0 + (size_t)32 * KTOT * j);
        #pragma unroll
        for (int j = 0; j < 4; j++) {
            unsigned r0 = tf32_bits(v[j].x), r1 = tf32_bits(v[j].y);
            unsigned r2 = tf32_bits(v[j].z), r3 = tf32_bits(v[j].w);
            unsigned byte = SW128((unsigned)((brow + 32 * j) * 128 + bq * 16));
            *(uint4*)(smem + byte) = make_uint4(r0, r1, r2, r3);
        }
    }
    __syncthreads();

    int buf = 0;
    for (int kt = 0; kt < 96; kt++) {
        const bool more = (kt + 1) < 96;
        float4 pf[4];
        if (more) {
            const float* src = bsrc0 + (size_t)(kt + 1) * 32;
            #pragma unroll
            for (int j = 0; j < 4; j++)
                pf[j] = *(const float4*)(src + (size_t)32 * KTOT * j);
        }

        const unsigned char* Bb = smem + buf * B_BUF_BYTES;
        const int koff_c = (kt >> 5) * (WR * 84) + (kt & 31) * 84;
        #pragma unroll
        for (int ks = 0; ks < 4; ks++) {
            const int koff = koff_c + ks * 8;
            unsigned b[4][2];
            #pragma unroll
            for (int nt2 = 0; nt2 < 4; nt2++) {
                int kb = ks * 32 + tig * 4;
                b[nt2][0] = *(const unsigned*)(Bb + nbase[nt2] + (kb ^ nxr[nt2]));
                b[nt2][1] = *(const unsigned*)(Bb + nbase[nt2] + ((kb + 16) ^ nxr[nt2]));
            }
            unsigned a[4][4];
            #pragma unroll
            for (int mt2 = 0; mt2 < 4; mt2++) {
                a[mt2][0] = img_w[abase[mt2][0] + koff];
                a[mt2][1] = img_w[abase[mt2][1] + koff];
                a[mt2][2] = img_w[abase[mt2][0] + koff + 4];
                a[mt2][3] = img_w[abase[mt2][1] + koff + 4];
            }
            #pragma unroll
            for (int mt2 = 0; mt2 < 4; mt2++)
                #pragma unroll
                for (int nt2 = 0; nt2 < 4; nt2++)
                    mma1688(acc[mt2][nt2], a[mt2], b[nt2]);
        }

        if (more) {
            unsigned char* Bn = smem + (buf ^ 1) * B_BUF_BYTES;
            #pragma unroll
            for (int j = 0; j < 4; j++) {
                unsigned r0 = tf32_bits(pf[j].x), r1 = tf32_bits(pf[j].y);
                unsigned r2 = tf32_bits(pf[j].z), r3 = tf32_bits(pf[j].w);
                unsigned byte = SW128((unsigned)((brow + 32 * j) * 128 + bq * 16));
                *(uint4*)(Bn + byte) = make_uint4(r0, r1, r2, r3);
            }
        }
        __syncthreads();
        buf ^= 1;
    }

    // ---- epilogue: dist = memsq - 2*score; store; block+global argmin
    float*    memsq_s = (float*)smem;            // reuse B buffers
    unsigned* amin_s  = (unsigned*)(smem + 512);
    if (tid < 128) {
        memsq_s[tid] = g_memsq[bn0 + tid];
        amin_s[tid]  = 0xFFFFFFFFu;
    }
    __syncthreads();

    #pragma unroll
    for (int mt2 = 0; mt2 < 4; mt2++)
        #pragma unroll
        for (int h = 0; h < 2; h++) {
            int pl = widm * 64 + mt2 * 16 + gid + 8 * h;
            int p  = pm0 + pl;
            if (p < NP) {
                unsigned lm = 0xFFFFFFFFu;
                #pragma unroll
                for (int nt2 = 0; nt2 < 4; nt2++) {
                    int nl = widn * 32 + nt2 * 8 + 2 * tig;
                    float d0 = memsq_s[nl]     - 2.f * acc[mt2][nt2][2 * h];
                    float d1 = memsq_s[nl + 1] - 2.f * acc[mt2][nt2][2 * h + 1];
                    *(float2*)(g_adist + (size_t)p * NM + bn0 + nl) =
                        make_float2(d0, d1);
                    unsigned e0 = enc(d0), e1 = enc(d1);
                    lm = min(lm, min(e0, e1));
                }
                atomicMin(&amin_s[pl], lm);
            }
        }
    __syncthreads();
    if (tid < 128 && pm0 + tid < NP)
        atomicMin(&g_amin[pm0 + tid], amin_s[tid]);
}

// ---------------------------------------------------------------------------
// K3: exact fp32 rescore of candidates within approx_min + T
// ---------------------------------------------------------------------------
#define CAND_CAP 512
__global__ __launch_bounds__(256)
void rescore_kernel(const float* __restrict__ image,
                    const float* __restrict__ mem,
                    const int* __restrict__ mapping) {
    __shared__ float patch_s[KTOT];
    __shared__ int   cand[CAND_CAP];
    __shared__ int   cnt;
    __shared__ float red[8];

    const int tid = threadIdx.x;
    const int p   = blockIdx.x;
    const int ph  = p / LHW;
    const int pw  = p - LHW * ph;

    for (int t = tid; t < KTOT; t += 256) {
        int c  = t >> 10;
        int kh = (t >> 5) & 31;
        int kw = t & 31;
        int I = ph + kh, J = pw + kw;     // padded coords
        float v = 0.f;
        if (I >= 10 && I < 74 && J >= 10 && J < 74)
            v = image[((I - 10) * 64 + (J - 10)) * 3 + c];
        patch_s[t] = v;
    }
    if (tid == 0) cnt = 0;
    __syncthreads();

    const float thr = dec(g_amin[p]) + 16.0f;
    const float* arow = g_adist + (size_t)p * NM;
    for (int n = tid; n < NM; n += 256) {
        if (arow[n] <= thr) {
            int i = atomicAdd(&cnt, 1);
            if (i < CAND_CAP) cand[i] = n;
        }
    }
    __syncthreads();
    int m = cnt < CAND_CAP ? cnt : CAND_CAP;
    if (tid == 0) {                       // ascending sort (tiny list)
        for (int i = 1; i < m; i++) {
            int v = cand[i], j = i - 1;
            while (j >= 0 && cand[j] > v) { cand[j + 1] = cand[j]; j--; }
            cand[j + 1] = v;
        }
    }
    __syncthreads();

    float bestd = 3.402823466e38f;
    int   bestn = 0;
    for (int i = 0; i < m; i++) {
        int n = cand[i];
        const float* mr = mem + (size_t)n * KTOT;
        float s = 0.f;
        for (int t = tid; t < KTOT; t += 256) s = fmaf(patch_s[t], mr[t], s);
        #pragma unroll
        for (int o = 16; o > 0; o >>= 1) s += __shfl_down_sync(0xFFFFFFFFu, s, o);
        if ((tid & 31) == 0) red[tid >> 5] = s;
        __syncthreads();
        if (tid == 0) {
            float tot = 0.f;
            #pragma unroll
            for (int w = 0; w < 8; w++) tot += red[w];
            float dist = g_memsq[n] - 2.f * tot;
            if (dist < bestd) { bestd = dist; bestn = n; }
        }
        __syncthreads();
    }
    if (tid == 0) g_rows[p] = mapping[bestn];
}

// ---------------------------------------------------------------------------
// K4a/K4b: deterministic overlap-add gather, kh-split
// ---------------------------------------------------------------------------
__global__ void recon_part_kernel(const float* __restrict__ mem2) {
    __shared__ int rows_s[NP];
    for (int t = threadIdx.x; t < NP; t += 256) rows_s[t] = g_rows[t];
    __syncthreads();
    int kh  = blockIdx.y;
    int idx = blockIdx.x * 256 + threadIdx.x;   // 0..12287
    int c = idx % 3;
    int j = (idx / 3) & 63;
    int i = idx / 192;
    int I = i + 10, J = j + 10;
    float s = 0.f;
    if (kh >= I - (LHW - 1) && kh <= min(31, I)) {
        int kwlo = max(0, J - (LHW - 1));
        int kwhi = min(31, J);
        int rbase = (I - kh) * LHW;
        int obase = c * 1024 + kh * 32;
        for (int kw = kwlo; kw <= kwhi; kw++) {
            int r = rows_s[rbase + (J - kw)];
            s += mem2[(size_t)r * KTOT + obase + kw];
        }
    }
    g_part[kh * 12288 + idx] = s;
}

__global__ void recon_sum_kernel(float* __restrict__ out) {
    int idx = blockIdx.x * 256 + threadIdx.x;
    float s = 0.f;
    #pragma unroll
    for (int kh = 0; kh < 32; kh++) s += g_part[kh * 12288 + idx];
    out[idx] = s;
}

// ---------------------------------------------------------------------------
// K5/K6: global max + scale
// ---------------------------------------------------------------------------
__global__ void max_kernel(const float* __restrict__ o) {
    float mx = -3.402823466e38f;
    for (int i = threadIdx.x; i < 12288; i += 1024) mx = fmaxf(mx, o[i]);
    #pragma unroll
    for (int off = 16; off > 0; off >>= 1)
        mx = fmaxf(mx, __shfl_xor_sync(0xFFFFFFFFu, mx, off));
    __shared__ float red[32];
    if ((threadIdx.x & 31) == 0) red[threadIdx.x >> 5] = mx;
    __syncthreads();
    if (threadIdx.x < 32) {
        mx = red[threadIdx.x];
        #pragma unroll
        for (int off = 16; off > 0; off >>= 1)
            mx = fmaxf(mx, __shfl_xor_sync(0xFFFFFFFFu, mx, off));
        if (threadIdx.x == 0) g_max = mx;
    }
}

__global__ void scale_kernel(float* __restrict__ o) {
    int i = blockIdx.x * 256 + threadIdx.x;
    if (i < 12288) o[i] = o[i] / g_max;
}

// ---------------------------------------------------------------------------
extern "C" void kernel_launch(void* const* d_in, const int* in_sizes, int n_in,
                              void* d_out, int out_size) {
    const float* image   = (const float*)d_in[0];
    const float* mem     = (const float*)d_in[1];
    const float* mem2    = (const float*)d_in[2];
    const int*   mapping = (const int*)d_in[3];
    float*       out     = (float*)d_out;

    cudaFuncSetAttribute(gemm_approx_kernel,
                         cudaFuncAttributeMaxDynamicSharedMemorySize, GEMM_SMEM);

    memsq_kernel<<<NM, 128>>>(mem);
    gemm_approx_kernel<<<dim3(64, 22), 256, GEMM_SMEM>>>(image, mem);
    rescore_kernel<<<NP, 256>>>(image, mem, mapping);
    recon_part_kernel<<<dim3(48, 32), 256>>>(mem2);
    recon_sum_kernel<<<48, 256>>>(out);
    max_kernel<<<1, 1024>>>(out);
    scale_kernel<<<48, 256>>>(out);
}

// round 5
// speedup vs baseline: 3.8212x; 1.0587x over previous
#include <cuda_runtime.h>
#include <cstdint>
#include <cstddef>

#define LHW   53
#define NP    2809
#define NM    8192
#define KTOT  3072
#define WR    35
#define IMG_ELEMS (3 * WR * 84)   // 8820

// ---------------- device scratch -------------------------------------------
__device__ unsigned  g_adist_bf[(size_t)NP * NM / 2];  // 46 MB bf16x2 approx dists
__device__ unsigned  g_amin[NP];
__device__ float     g_memsq[NM];
__device__ int       g_rows[NP];
__device__ float     g_part[32 * 12288];
__device__ float     g_max;

__device__ __forceinline__ unsigned enc(float x) {
    unsigned u = __float_as_uint(x);
    return (u & 0x80000000u) ? ~u : (u | 0x80000000u);
}
__device__ __forceinline__ float dec(unsigned u) {
    unsigned b = (u & 0x80000000u) ? (u & 0x7FFFFFFFu) : ~u;
    return __uint_as_float(b);
}
__device__ __forceinline__ unsigned pack_bf16x2(float lo, float hi) {
    unsigned r;
    asm("cvt.rn.bf16x2.f32 %0, %1, %2;" : "=r"(r) : "f"(hi), "f"(lo));
    return r;
}
__device__ __forceinline__ void mma16816(float* d, const unsigned* a, const unsigned* b) {
    asm volatile(
        "mma.sync.aligned.m16n8k16.row.col.f32.bf16.bf16.f32 "
        "{%0,%1,%2,%3}, {%4,%5,%6,%7}, {%8,%9}, {%0,%1,%2,%3};"
        : "+f"(d[0]), "+f"(d[1]), "+f"(d[2]), "+f"(d[3])
        : "r"(a[0]), "r"(a[1]), "r"(a[2]), "r"(a[3]), "r"(b[0]), "r"(b[1]));
}

// ---------------------------------------------------------------------------
// K1: mem_sq from ORIGINAL fp32 mem; init g_amin
// ---------------------------------------------------------------------------
__global__ void memsq_kernel(const float* __restrict__ mem) {
    int n = blockIdx.x;
    const float* row = mem + (size_t)n * KTOT;
    float s = 0.f;
    for (int i = threadIdx.x; i < KTOT; i += 128) {
        float v = row[i];
        s = fmaf(v, v, s);
    }
    #pragma unroll
    for (int o = 16; o > 0; o >>= 1) s += __shfl_down_sync(0xFFFFFFFFu, s, o);
    __shared__ float part[4];
    if ((threadIdx.x & 31) == 0) part[threadIdx.x >> 5] = s;
    __syncthreads();
    if (threadIdx.x == 0) g_memsq[n] = (part[0] + part[1]) + (part[2] + part[3]);
    if (threadIdx.x == 32 && n < NP) g_amin[n] = 0xFFFFFFFFu;
}

// ---------------------------------------------------------------------------
// K2: bf16 mma.sync approx GEMM. CTA 128x128, K in 32-chunks (2 k16-steps).
// B staged in smem in FRAG layout [ks][reg][n][tig] -> conflict-free 128B LDS.
// A synthesized per-lane from packed-bf16x2 image window.
// ---------------------------------------------------------------------------
#define B_BUF_BYTES 8192
#define IMG_OFF     16384
#define GEMM_SMEM   (IMG_OFF + IMG_ELEMS * 4)   // 51664

__device__ __forceinline__ float imgval(const float* __restrict__ image,
                                        int rlo, int idx) {
    int c   = idx / (WR * 84);
    int rem = idx - c * (WR * 84);
    int il  = rem / 84;
    int j   = rem - il * 84;
    int I   = rlo + il;
    float v = 0.f;
    if (I >= 10 && I < 74 && j >= 10 && j < 74)
        v = image[((I - 10) * 64 + (j - 10)) * 3 + c];
    return v;
}

__global__ __launch_bounds__(256, 2)
void gemm_approx_kernel(const float* __restrict__ image,
                        const float* __restrict__ mem) {
    extern __shared__ __align__(1024) unsigned char smem[];
    unsigned* img_p = (unsigned*)(smem + IMG_OFF);   // packed bf16x2 pairs

    const int tid  = threadIdx.x;
    const int lane = tid & 31;
    const int wid  = tid >> 5;
    const int widm = wid >> 2;        // 0..1
    const int widn = wid & 3;         // 0..3
    const int gid  = lane >> 2;       // 0..7
    const int tig  = lane & 3;        // 0..3

    const int bn0 = blockIdx.x * 128;
    const int pm0 = blockIdx.y * 128;
    const int rlo = pm0 / LHW;

    // packed image window pairs: img_p[j] = {bf16(img[j]), bf16(img[j+1])}
    for (int idx = tid; idx < IMG_ELEMS; idx += 256) {
        float v0 = imgval(image, rlo, idx);
        float v1 = (idx + 1 < IMG_ELEMS) ? imgval(image, rlo, idx + 1) : 0.f;
        img_p[idx] = pack_bf16x2(v0, v1);
    }

    // per-lane A row bases (element index of (kh=0,kw=0) for each m-frag row)
    int abase[4][2];
    #pragma unroll
    for (int mt2 = 0; mt2 < 4; mt2++)
        #pragma unroll
        for (int h = 0; h < 2; h++) {
            int pr = pm0 + widm * 64 + mt2 * 16 + gid + 8 * h;
            pr = pr < NP ? pr : NP - 1;
            int ph = pr / LHW;
            abase[mt2][h] = (ph - rlo) * 84 + (pr - LHW * ph);
        }

    // B fill mapping: thread t handles row n = t>>1, k-half = t&1 (16 floats)
    const int bfn   = tid >> 1;
    const int bfh   = tid & 1;
    const float* bsrc0 = mem + (size_t)(bn0 + bfn) * KTOT + bfh * 16;

    // B frag n-columns for this warp
    int nl[4];
    #pragma unroll
    for (int nt2 = 0; nt2 < 4; nt2++) nl[nt2] = widn * 32 + nt2 * 8 + gid;

    float acc[4][4][4];
    #pragma unroll
    for (int i = 0; i < 4; i++)
        #pragma unroll
        for (int j = 0; j < 4; j++)
            #pragma unroll
            for (int k = 0; k < 4; k++) acc[i][j][k] = 0.f;

    // --- helpers to convert+store one thread's B slice into frag layout ----
    // Bfrag[half][r][n][tig] (uint32) ; offset = ((half*2+r)*128 + n)*4 + tig
    // prologue chunk 0 -> buffer 0
    {
        float f[16];
        #pragma unroll
        for (int j = 0; j < 4; j++)
            *(float4*)(f + 4 * j) = *(const float4*)(bsrc0 + 4 * j);
        unsigned* Bb = (unsigned*)smem;
        #pragma unroll
        for (int r = 0; r < 2; r++) {
            uint4 st;
            st.x = pack_bf16x2(f[r * 8 + 0], f[r * 8 + 1]);
            st.y = pack_bf16x2(f[r * 8 + 2], f[r * 8 + 3]);
            st.z = pack_bf16x2(f[r * 8 + 4], f[r * 8 + 5]);
            st.w = pack_bf16x2(f[r * 8 + 6], f[r * 8 + 7]);
            *(uint4*)(Bb + ((bfh * 2 + r) * 128 + bfn) * 4) = st;
        }
    }
    __syncthreads();

    int buf = 0;
    for (int kt = 0; kt < 96; kt++) {
        const bool more = (kt + 1) < 96;
        float f[16];
        if (more) {
            const float* src = bsrc0 + (size_t)(kt + 1) * 32;
            #pragma unroll
            for (int j = 0; j < 4; j++)
                *(float4*)(f + 4 * j) = *(const float4*)(src + 4 * j);
        }

        const unsigned* Bb = (const unsigned*)(smem + buf * B_BUF_BYTES);
        const int koff_c = (kt >> 5) * (WR * 84) + (kt & 31) * 84;
        #pragma unroll
        for (int ks = 0; ks < 2; ks++) {
            unsigned b[4][2];
            #pragma unroll
            for (int nt2 = 0; nt2 < 4; nt2++) {
                b[nt2][0] = Bb[((ks * 2 + 0) * 128 + nl[nt2]) * 4 + tig];
                b[nt2][1] = Bb[((ks * 2 + 1) * 128 + nl[nt2]) * 4 + tig];
            }
            const int K0 = koff_c + ks * 16 + 2 * tig;
            unsigned a[4][4];
            #pragma unroll
            for (int mt2 = 0; mt2 < 4; mt2++) {
                a[mt2][0] = img_p[abase[mt2][0] + K0];
                a[mt2][1] = img_p[abase[mt2][1] + K0];
                a[mt2][2] = img_p[abase[mt2][0] + K0 + 8];
                a[mt2][3] = img_p[abase[mt2][1] + K0 + 8];
            }
            #pragma unroll
            for (int mt2 = 0; mt2 < 4; mt2++)
                #pragma unroll
                for (int nt2 = 0; nt2 < 4; nt2++)
                    mma16816(acc[mt2][nt2], a[mt2], b[nt2]);
        }

        if (more) {
            unsigned* Bn = (unsigned*)(smem + (buf ^ 1) * B_BUF_BYTES);
            #pragma unroll
            for (int r = 0; r < 2; r++) {
                uint4 st;
                st.x = pack_bf16x2(f[r * 8 + 0], f[r * 8 + 1]);
                st.y = pack_bf16x2(f[r * 8 + 2], f[r * 8 + 3]);
                st.z = pack_bf16x2(f[r * 8 + 4], f[r * 8 + 5]);
                st.w = pack_bf16x2(f[r * 8 + 6], f[r * 8 + 7]);
                *(uint4*)(Bn + ((bfh * 2 + r) * 128 + bfn) * 4) = st;
            }
        }
        __syncthreads();
        buf ^= 1;
    }

    // ---- epilogue: dist = memsq - 2*score; store bf16x2; block+global argmin
    float*    memsq_s = (float*)smem;
    unsigned* amin_s  = (unsigned*)(smem + 512);
    if (tid < 128) {
        memsq_s[tid] = g_memsq[bn0 + tid];
        amin_s[tid]  = 0xFFFFFFFFu;
    }
    __syncthreads();

    #pragma unroll
    for (int mt2 = 0; mt2 < 4; mt2++)
        #pragma unroll
        for (int h = 0; h < 2; h++) {
            int pl = widm * 64 + mt2 * 16 + gid + 8 * h;
            int p  = pm0 + pl;
            if (p < NP) {
                unsigned lm = 0xFFFFFFFFu;
                #pragma unroll
                for (int nt2 = 0; nt2 < 4; nt2++) {
                    int n2 = widn * 32 + nt2 * 8 + 2 * tig;
                    float d0 = memsq_s[n2]     - 2.f * acc[mt2][nt2][2 * h];
                    float d1 = memsq_s[n2 + 1] - 2.f * acc[mt2][nt2][2 * h + 1];
                    g_adist_bf[((size_t)p * NM + bn0 + n2) >> 1] = pack_bf16x2(d0, d1);
                    lm = min(lm, min(enc(d0), enc(d1)));
                }
                atomicMin(&amin_s[pl], lm);
            }
        }
    __syncthreads();
    if (tid < 128 && pm0 + tid < NP)
        atomicMin(&g_amin[pm0 + tid], amin_s[tid]);
}

// ---------------------------------------------------------------------------
// K3: exact fp32 rescore of candidates within approx_min + T
// ---------------------------------------------------------------------------
#define CAND_CAP 512
#define THRESH   64.0f
__global__ __launch_bounds__(256)
void rescore_kernel(const float* __restrict__ image,
                    const float* __restrict__ mem,
                    const int* __restrict__ mapping) {
    __shared__ float patch_s[KTOT];
    __shared__ int   cand[CAND_CAP];
    __shared__ int   cnt;
    __shared__ float red[8];

    const int tid = threadIdx.x;
    const int p   = blockIdx.x;
    const int ph  = p / LHW;
    const int pw  = p - LHW * ph;

    for (int t = tid; t < KTOT; t += 256) {
        int c  = t >> 10;
        int kh = (t >> 5) & 31;
        int kw = t & 31;
        int I = ph + kh, J = pw + kw;
        float v = 0.f;
        if (I >= 10 && I < 74 && J >= 10 && J < 74)
            v = image[((I - 10) * 64 + (J - 10)) * 3 + c];
        patch_s[t] = v;
    }
    if (tid == 0) cnt = 0;
    __syncthreads();

    const float thr = dec(g_amin[p]) + THRESH;
    const unsigned* arow = g_adist_bf + ((size_t)p * NM >> 1);
    for (int i = tid; i < NM / 2; i += 256) {
        unsigned w = arow[i];
        float lo = __uint_as_float(w << 16);
        float hi = __uint_as_float(w & 0xFFFF0000u);
        if (lo <= thr) { int k = atomicAdd(&cnt, 1); if (k < CAND_CAP) cand[k] = 2 * i; }
        if (hi <= thr) { int k = atomicAdd(&cnt, 1); if (k < CAND_CAP) cand[k] = 2 * i + 1; }
    }
    __syncthreads();
    int m = cnt < CAND_CAP ? cnt : CAND_CAP;
    if (tid == 0) {
        for (int i = 1; i < m; i++) {
            int v = cand[i], j = i - 1;
            while (j >= 0 && cand[j] > v) { cand[j + 1] = cand[j]; j--; }
            cand[j + 1] = v;
        }
    }
    __syncthreads();

    float bestd = 3.402823466e38f;
    int   bestn = 0;
    for (int i = 0; i < m; i++) {
        int n = cand[i];
        const float* mr = mem + (size_t)n * KTOT;
        float s = 0.f;
        for (int t = tid; t < KTOT; t += 256) s = fmaf(patch_s[t], mr[t], s);
        #pragma unroll
        for (int o = 16; o > 0; o >>= 1) s += __shfl_down_sync(0xFFFFFFFFu, s, o);
        if ((tid & 31) == 0) red[tid >> 5] = s;
        __syncthreads();
        if (tid == 0) {
            float tot = 0.f;
            #pragma unroll
            for (int w = 0; w < 8; w++) tot += red[w];
            float dist = g_memsq[n] - 2.f * tot;
            if (dist < bestd) { bestd = dist; bestn = n; }
        }
        __syncthreads();
    }
    if (tid == 0) g_rows[p] = mapping[bestn];
}

// ---------------------------------------------------------------------------
// K4a/K4b: deterministic overlap-add gather, kh-split
// ---------------------------------------------------------------------------
__global__ void recon_part_kernel(const float* __restrict__ mem2) {
    __shared__ int rows_s[NP];
    for (int t = threadIdx.x; t < NP; t += 256) rows_s[t] = g_rows[t];
    __syncthreads();
    int kh  = blockIdx.y;
    int idx = blockIdx.x * 256 + threadIdx.x;
    int c = idx % 3;
    int j = (idx / 3) & 63;
    int i = idx / 192;
    int I = i + 10, J = j + 10;
    float s = 0.f;
    if (kh >= I - (LHW - 1) && kh <= min(31, I)) {
        int kwlo = max(0, J - (LHW - 1));
        int kwhi = min(31, J);
        int rbase = (I - kh) * LHW;
        int obase = c * 1024 + kh * 32;
        for (int kw = kwlo; kw <= kwhi; kw++) {
            int r = rows_s[rbase + (J - kw)];
            s += mem2[(size_t)r * KTOT + obase + kw];
        }
    }
    g_part[kh * 12288 + idx] = s;
}

__global__ void recon_sum_kernel(float* __restrict__ out) {
    int idx = blockIdx.x * 256 + threadIdx.x;
    float s = 0.f;
    #pragma unroll
    for (int kh = 0; kh < 32; kh++) s += g_part[kh * 12288 + idx];
    out[idx] = s;
}

// ---------------------------------------------------------------------------
// K5/K6: global max + scale
// ---------------------------------------------------------------------------
__global__ void max_kernel(const float* __restrict__ o) {
    float mx = -3.402823466e38f;
    for (int i = threadIdx.x; i < 12288; i += 1024) mx = fmaxf(mx, o[i]);
    #pragma unroll
    for (int off = 16; off > 0; off >>= 1)
        mx = fmaxf(mx, __shfl_xor_sync(0xFFFFFFFFu, mx, off));
    __shared__ float red[32];
    if ((threadIdx.x & 31) == 0) red[threadIdx.x >> 5] = mx;
    __syncthreads();
    if (threadIdx.x < 32) {
        mx = red[threadIdx.x];
        #pragma unroll
        for (int off = 16; off > 0; off >>= 1)
            mx = fmaxf(mx, __shfl_xor_sync(0xFFFFFFFFu, mx, off));
        if (threadIdx.x == 0) g_max = mx;
    }
}

__global__ void scale_kernel(float* __restrict__ o) {
    int i = blockIdx.x * 256 + threadIdx.x;
    if (i < 12288) o[i] = o[i] / g_max;
}

// ---------------------------------------------------------------------------
extern "C" void kernel_launch(void* const* d_in, const int* in_sizes, int n_in,
                              void* d_out, int out_size) {
    const float* image   = (const float*)d_in[0];
    const float* mem     = (const float*)d_in[1];
    const float* mem2    = (const float*)d_in[2];
    const int*   mapping = (const int*)d_in[3];
    float*       out     = (float*)d_out;

    cudaFuncSetAttribute(gemm_approx_kernel,
                         cudaFuncAttributeMaxDynamicSharedMemorySize, GEMM_SMEM);

    memsq_kernel<<<NM, 128>>>(mem);
    gemm_approx_kernel<<<dim3(64, 22), 256, GEMM_SMEM>>>(image, mem);
    rescore_kernel<<<NP, 256>>>(image, mem, mapping);
    recon_part_kernel<<<dim3(48, 32), 256>>>(mem2);
    recon_sum_kernel<<<48, 256>>>(out);
    max_kernel<<<1, 1024>>>(out);
    scale_kernel<<<48, 256>>>(out);
}